// round 2
// baseline (speedup 1.0000x reference)
#include <cuda_runtime.h>
#include <cuda_bf16.h>
#include <math.h>

#define VV 50000
#define EE 512
#define HH 512
#define BB 128
#define SS 256
#define OOV 12
#define VEXT (VV + OOV)   // 50012

// ---------------- scratch (device globals; no allocation) ----------------
#define OFF_XEMB   0                                 // B*E
#define OFF_PREV   (OFF_XEMB + BB*EE)                // B*H
#define OFF_GI     (OFF_PREV + BB*HH)                // B*3H
#define OFF_GH     (OFF_GI + BB*3*HH)
#define OFF_STATE  (OFF_GH + BB*3*HH)                // B*H
#define OFF_SATT   (OFF_STATE + BB*HH)               // B*H
#define OFF_ENERGY (OFF_SATT + BB*HH)                // B*S
#define OFF_ATTNW  (OFF_ENERGY + BB*SS)              // B*S
#define OFF_Y      (OFF_ATTNW + BB*SS)               // B*2H
#define OFF_SCOREG (OFF_Y + BB*2*HH)                 // B*V
#define OFF_SCOREC (OFF_SCOREG + (size_t)BB*VV)      // B*S
#define OFF_PROBC  (OFF_SCOREC + BB*SS)              // B*S
#define OFF_M      (OFF_PROBC + BB*SS)               // B
#define OFF_Z      (OFF_M + BB)                      // B
#define OFF_PCSUM  (OFF_Z + BB)                      // 1
#define SCRATCH_FLOATS (OFF_PCSUM + 64)

__device__ float g_scratch[SCRATCH_FLOATS];

// packed fp32x2 FMA (Blackwell): 2 FMAs per instruction per lane
__device__ __forceinline__ void ffma2(unsigned long long &c,
                                      unsigned long long a,
                                      unsigned long long b) {
    asm("fma.rn.f32x2 %0, %1, %2, %0;" : "+l"(c) : "l"(a), "l"(b));
}
struct __align__(16) ull2 { unsigned long long x, y; };
__device__ __forceinline__ float f2lo(unsigned long long v) {
    return __uint_as_float((unsigned int)v);
}
__device__ __forceinline__ float f2hi(unsigned long long v) {
    return __uint_as_float((unsigned int)(v >> 32));
}

// ---------------- zero scratch region ----------------
__global__ __launch_bounds__(256)
void zero_kernel(float* __restrict__ p, int n) {
    int i = blockIdx.x * 256 + threadIdx.x;
    if (i < n) p[i] = 0.f;
}

// ---------------- embed gather ----------------
__global__ __launch_bounds__(512)
void gather_embed(const int* __restrict__ idx, const float* __restrict__ tab,
                  float* __restrict__ x)
{
    int b = blockIdx.x, t = threadIdx.x;
    x[b * EE + t] = tab[(long)idx[b] * EE + t];
}

// ---------------- small GEMM, split-K, atomic accumulate ----------------
// C[m,n] += A[m,ks:ks+kl] @ W[n,ks:ks+kl]^T   (+bias if blockIdx.y==0)
// M = 128 fixed. C must be pre-zeroed.
__global__ __launch_bounds__(256)
void gemm128_splitk(const float* __restrict__ A, int lda,
                    const float* __restrict__ W, int ldw,
                    const float* __restrict__ bias,
                    float* __restrict__ C, int N, int Ktot)
{
    __shared__ float Asm[16][132];
    __shared__ float Wd[16][136];
    const int tid = threadIdx.x;
    const int ty = tid >> 4, tx = tid & 15;
    const int n0 = blockIdx.x * 64;
    const int kl = Ktot / gridDim.y;
    const int ks = blockIdx.y * kl;
    const int am  = tid >> 2;
    const int akv = (tid & 3) << 2;
    const int wn  = tid >> 2;
    const int wkv = (tid & 3) << 2;

    unsigned long long acc[4][4];
#pragma unroll
    for (int i = 0; i < 4; i++)
#pragma unroll
        for (int j = 0; j < 4; j++) acc[i][j] = 0ull;

    for (int k0 = ks; k0 < ks + kl; k0 += 16) {
        __syncthreads();
#pragma unroll
        for (int r = 0; r < 2; r++) {
            int m = am + r * 64;
            float4 v = *(const float4*)&A[(size_t)m * lda + k0 + akv];
            Asm[akv+0][m] = v.x; Asm[akv+1][m] = v.y;
            Asm[akv+2][m] = v.z; Asm[akv+3][m] = v.w;
        }
        {
            float4 v = *(const float4*)&W[(size_t)(n0 + wn) * ldw + k0 + wkv];
            Wd[wkv+0][2*wn] = v.x; Wd[wkv+0][2*wn+1] = v.x;
            Wd[wkv+1][2*wn] = v.y; Wd[wkv+1][2*wn+1] = v.y;
            Wd[wkv+2][2*wn] = v.z; Wd[wkv+2][2*wn+1] = v.z;
            Wd[wkv+3][2*wn] = v.w; Wd[wkv+3][2*wn+1] = v.w;
        }
        __syncthreads();
#pragma unroll
        for (int kk = 0; kk < 16; kk++) {
            ull2 a01 = *(const ull2*)&Asm[kk][ty*8];
            ull2 a23 = *(const ull2*)&Asm[kk][ty*8+4];
            ull2 w01 = *(const ull2*)&Wd[kk][tx*8];
            ull2 w23 = *(const ull2*)&Wd[kk][tx*8+4];
            ffma2(acc[0][0], a01.x, w01.x); ffma2(acc[0][1], a01.x, w01.y);
            ffma2(acc[0][2], a01.x, w23.x); ffma2(acc[0][3], a01.x, w23.y);
            ffma2(acc[1][0], a01.y, w01.x); ffma2(acc[1][1], a01.y, w01.y);
            ffma2(acc[1][2], a01.y, w23.x); ffma2(acc[1][3], a01.y, w23.y);
            ffma2(acc[2][0], a23.x, w01.x); ffma2(acc[2][1], a23.x, w01.y);
            ffma2(acc[2][2], a23.x, w23.x); ffma2(acc[2][3], a23.x, w23.y);
            ffma2(acc[3][0], a23.y, w01.x); ffma2(acc[3][1], a23.y, w01.y);
            ffma2(acc[3][2], a23.y, w23.x); ffma2(acc[3][3], a23.y, w23.y);
        }
    }
#pragma unroll
    for (int r2 = 0; r2 < 4; r2++) {
#pragma unroll
        for (int j = 0; j < 4; j++) {
            int n = n0 + tx * 4 + j;
            float bsum = (blockIdx.y == 0 && bias) ? bias[n] : 0.f;
            int m0 = ty * 8 + 2 * r2;
            atomicAdd(&C[(size_t)m0 * N + n],       f2lo(acc[r2][j]) + bsum);
            atomicAdd(&C[(size_t)(m0 + 1) * N + n], f2hi(acc[r2][j]) + bsum);
        }
    }
}

// ---------------- GRU elementwise ----------------
__global__ __launch_bounds__(256)
void gru_kernel(const float* __restrict__ gi, const float* __restrict__ gh,
                const float* __restrict__ prev,
                float* __restrict__ state, float* __restrict__ y,
                float* __restrict__ out_state)
{
    int i = blockIdx.x * 256 + threadIdx.x;
    int b = i / HH, h = i - b * HH;
    const float* gib = gi + b * 3 * HH;
    const float* ghb = gh + b * 3 * HH;
    float i_r = gib[h],          h_r = ghb[h];
    float i_z = gib[HH + h],     h_z = ghb[HH + h];
    float i_n = gib[2 * HH + h], h_n = ghb[2 * HH + h];
    float r = 1.f / (1.f + expf(-(i_r + h_r)));
    float z = 1.f / (1.f + expf(-(i_z + h_z)));
    float n = tanhf(i_n + r * h_n);
    float st = (1.f - z) * n + z * prev[i];
    state[i] = st;
    y[b * (2 * HH) + h] = st;
    out_state[i] = st;
}

// ---------------- fused: out[r] = sum_n tanh((A@W^T)[r,n] + add[n]) * wv[n] --
// 128 rows per block (same b), f32x2 inner loop, K = 512.
__global__ __launch_bounds__(256)
void fused_tanh_dot_v2(const float* __restrict__ A,
                       const float* __restrict__ W, int ldw,
                       const float* __restrict__ addg, int add_per_b,
                       const float* __restrict__ wvg, int wv_per_b,
                       const int* __restrict__ maskidx,
                       int Ntot, float* __restrict__ outv)
{
    const int row0 = blockIdx.x * 128;
    const int b = row0 >> 8;
    __shared__ float Asm[16][132];
    __shared__ float Wd[16][136];
    __shared__ float addv[64];
    __shared__ float wvv[64];
    __shared__ float red[128][17];
    const int tid = threadIdx.x;
    const int ty = tid >> 4, tx = tid & 15;
    const int am  = tid >> 2;
    const int akv = (tid & 3) << 2;
    const int wn  = tid >> 2;
    const int wkv = (tid & 3) << 2;

    float partial[8];
#pragma unroll
    for (int i = 0; i < 8; i++) partial[i] = 0.f;

    for (int n0 = 0; n0 < Ntot; n0 += 64) {
        __syncthreads();
        if (tid < 64) {
            addv[tid] = add_per_b ? addg[b * Ntot + n0 + tid] : addg[n0 + tid];
            wvv[tid]  = wv_per_b  ? wvg[b * Ntot + n0 + tid]  : wvg[n0 + tid];
        }
        unsigned long long acc[4][4];
#pragma unroll
        for (int i = 0; i < 4; i++)
#pragma unroll
            for (int j = 0; j < 4; j++) acc[i][j] = 0ull;

        for (int k0 = 0; k0 < 512; k0 += 16) {
            __syncthreads();
#pragma unroll
            for (int r = 0; r < 2; r++) {
                int m = am + r * 64;
                float4 v = *(const float4*)&A[(size_t)(row0 + m) * 512 + k0 + akv];
                Asm[akv+0][m] = v.x; Asm[akv+1][m] = v.y;
                Asm[akv+2][m] = v.z; Asm[akv+3][m] = v.w;
            }
            {
                float4 v = *(const float4*)&W[(size_t)(n0 + wn) * ldw + k0 + wkv];
                Wd[wkv+0][2*wn] = v.x; Wd[wkv+0][2*wn+1] = v.x;
                Wd[wkv+1][2*wn] = v.y; Wd[wkv+1][2*wn+1] = v.y;
                Wd[wkv+2][2*wn] = v.z; Wd[wkv+2][2*wn+1] = v.z;
                Wd[wkv+3][2*wn] = v.w; Wd[wkv+3][2*wn+1] = v.w;
            }
            __syncthreads();
#pragma unroll
            for (int kk = 0; kk < 16; kk++) {
                ull2 a01 = *(const ull2*)&Asm[kk][ty*8];
                ull2 a23 = *(const ull2*)&Asm[kk][ty*8+4];
                ull2 w01 = *(const ull2*)&Wd[kk][tx*8];
                ull2 w23 = *(const ull2*)&Wd[kk][tx*8+4];
                ffma2(acc[0][0], a01.x, w01.x); ffma2(acc[0][1], a01.x, w01.y);
                ffma2(acc[0][2], a01.x, w23.x); ffma2(acc[0][3], a01.x, w23.y);
                ffma2(acc[1][0], a01.y, w01.x); ffma2(acc[1][1], a01.y, w01.y);
                ffma2(acc[1][2], a01.y, w23.x); ffma2(acc[1][3], a01.y, w23.y);
                ffma2(acc[2][0], a23.x, w01.x); ffma2(acc[2][1], a23.x, w01.y);
                ffma2(acc[2][2], a23.x, w23.x); ffma2(acc[2][3], a23.x, w23.y);
                ffma2(acc[3][0], a23.y, w01.x); ffma2(acc[3][1], a23.y, w01.y);
                ffma2(acc[3][2], a23.y, w23.x); ffma2(acc[3][3], a23.y, w23.y);
            }
        }
        // epilogue: tanh + dot with wv
        __syncthreads();  // addv/wvv fully written
#pragma unroll
        for (int r2 = 0; r2 < 4; r2++) {
#pragma unroll
            for (int j = 0; j < 4; j++) {
                int n = tx * 4 + j;
                float ad = addv[n], wq = wvv[n];
                partial[2*r2]   += tanhf(f2lo(acc[r2][j]) + ad) * wq;
                partial[2*r2+1] += tanhf(f2hi(acc[r2][j]) + ad) * wq;
            }
        }
    }
    __syncthreads();
#pragma unroll
    for (int i = 0; i < 8; i++) red[ty * 8 + i][tx] = partial[i];
    __syncthreads();
    if (tid < 128) {
        float s = 0.f;
#pragma unroll
        for (int j = 0; j < 16; j++) s += red[tid][j];
        int r = row0 + tid;
        if (maskidx && maskidx[r] == 0) s -= 1000.f;
        outv[r] = s;
    }
}

// ---------------- score_g: [128,50000] = y[128,1024] @ Wo^T + Wo_b ----------
__global__ __launch_bounds__(256)
void scoreg_v2(const float* __restrict__ y, const float* __restrict__ Wo,
               const float* __restrict__ Wob, float* __restrict__ outg)
{
    __shared__ float Asm[16][132];
    __shared__ float Wd[16][136];
    const int tid = threadIdx.x;
    const int ty = tid >> 4, tx = tid & 15;
    const int n0 = blockIdx.x * 64;
    const int am  = tid >> 2;
    const int akv = (tid & 3) << 2;
    const int wn  = tid >> 2;
    const int wkv = (tid & 3) << 2;

    unsigned long long acc[4][4];
#pragma unroll
    for (int i = 0; i < 4; i++)
#pragma unroll
        for (int j = 0; j < 4; j++) acc[i][j] = 0ull;

    for (int k0 = 0; k0 < 1024; k0 += 16) {
        __syncthreads();
#pragma unroll
        for (int r = 0; r < 2; r++) {
            int m = am + r * 64;
            float4 v = *(const float4*)&y[(size_t)m * 1024 + k0 + akv];
            Asm[akv+0][m] = v.x; Asm[akv+1][m] = v.y;
            Asm[akv+2][m] = v.z; Asm[akv+3][m] = v.w;
        }
        {
            int ng = n0 + wn;
            float4 v = make_float4(0.f, 0.f, 0.f, 0.f);
            if (ng < VV) v = *(const float4*)&Wo[(size_t)ng * 1024 + k0 + wkv];
            Wd[wkv+0][2*wn] = v.x; Wd[wkv+0][2*wn+1] = v.x;
            Wd[wkv+1][2*wn] = v.y; Wd[wkv+1][2*wn+1] = v.y;
            Wd[wkv+2][2*wn] = v.z; Wd[wkv+2][2*wn+1] = v.z;
            Wd[wkv+3][2*wn] = v.w; Wd[wkv+3][2*wn+1] = v.w;
        }
        __syncthreads();
#pragma unroll
        for (int kk = 0; kk < 16; kk++) {
            ull2 a01 = *(const ull2*)&Asm[kk][ty*8];
            ull2 a23 = *(const ull2*)&Asm[kk][ty*8+4];
            ull2 w01 = *(const ull2*)&Wd[kk][tx*8];
            ull2 w23 = *(const ull2*)&Wd[kk][tx*8+4];
            ffma2(acc[0][0], a01.x, w01.x); ffma2(acc[0][1], a01.x, w01.y);
            ffma2(acc[0][2], a01.x, w23.x); ffma2(acc[0][3], a01.x, w23.y);
            ffma2(acc[1][0], a01.y, w01.x); ffma2(acc[1][1], a01.y, w01.y);
            ffma2(acc[1][2], a01.y, w23.x); ffma2(acc[1][3], a01.y, w23.y);
            ffma2(acc[2][0], a23.x, w01.x); ffma2(acc[2][1], a23.x, w01.y);
            ffma2(acc[2][2], a23.x, w23.x); ffma2(acc[2][3], a23.x, w23.y);
            ffma2(acc[3][0], a23.y, w01.x); ffma2(acc[3][1], a23.y, w01.y);
            ffma2(acc[3][2], a23.y, w23.x); ffma2(acc[3][3], a23.y, w23.y);
        }
    }
#pragma unroll
    for (int r2 = 0; r2 < 4; r2++) {
#pragma unroll
        for (int j = 0; j < 4; j++) {
            int n = n0 + tx * 4 + j;
            if (n < VV) {
                float bsum = Wob[n];
                int m0 = ty * 8 + 2 * r2;
                outg[(size_t)m0 * VV + n]       = f2lo(acc[r2][j]) + bsum;
                outg[(size_t)(m0 + 1) * VV + n] = f2hi(acc[r2][j]) + bsum;
            }
        }
    }
}

// ---------------- attn softmax over S ----------------
__global__ __launch_bounds__(256)
void softmax_s_kernel(const float* __restrict__ e, float* __restrict__ w)
{
    int b = blockIdx.x, t = threadIdx.x;
    __shared__ float sm[256];
    __shared__ float bc;
    float x = e[b * SS + t];
    sm[t] = x; __syncthreads();
    for (int o = 128; o > 0; o >>= 1) { if (t < o) sm[t] = fmaxf(sm[t], sm[t + o]); __syncthreads(); }
    if (t == 0) bc = sm[0];
    __syncthreads();
    float ex = expf(x - bc);
    __syncthreads();
    sm[t] = ex; __syncthreads();
    for (int o = 128; o > 0; o >>= 1) { if (t < o) sm[t] += sm[t + o]; __syncthreads(); }
    if (t == 0) bc = sm[0];
    __syncthreads();
    w[b * SS + t] = ex / bc;
}

// ---------------- context = sum_s attnw * encoded (into y[:,H:]) -----------
__global__ __launch_bounds__(512)
void context_kernel(const float* __restrict__ aw, const float* __restrict__ enc,
                    float* __restrict__ y)
{
    int b = blockIdx.x, h = threadIdx.x;
    __shared__ float c[256];
    if (h < 256) c[h] = aw[b * SS + h];
    __syncthreads();
    float acc = 0.f;
    const float* eb = enc + (size_t)b * SS * HH + h;
#pragma unroll 4
    for (int s = 0; s < SS; s++) acc += c[s] * eb[s * HH];
    y[b * (2 * HH) + HH + h] = acc;
}

// ---------------- online row max + sumexp over concat(score_g, score_c) ----
__global__ __launch_bounds__(256)
void rowmaxsum_kernel(const float* __restrict__ g, const float* __restrict__ c,
                      float* __restrict__ mout, float* __restrict__ zout)
{
    int b = blockIdx.x, t = threadIdx.x;
    float m = -1e30f, z = 0.f;
    const float* gb = g + (size_t)b * VV;
    for (int j = t; j < VV; j += 256) {
        float x = gb[j];
        if (x > m) { z = z * expf(m - x) + 1.f; m = x; }
        else z += expf(x - m);
    }
    {
        float x = c[b * SS + t];
        if (x > m) { z = z * expf(m - x) + 1.f; m = x; }
        else z += expf(x - m);
    }
    __shared__ float sm[256], sz[256];
    sm[t] = m; sz[t] = z; __syncthreads();
    for (int o = 128; o > 0; o >>= 1) {
        if (t < o) {
            float m1 = sm[t], m2 = sm[t + o];
            float M = fmaxf(m1, m2);
            sz[t] = sz[t] * expf(m1 - M) + sz[t + o] * expf(m2 - M);
            sm[t] = M;
        }
        __syncthreads();
    }
    if (t == 0) { mout[b] = sm[0]; zout[b] = sz[0]; }
}

// ---------------- write prob_g_ext into out ----------------
__global__ __launch_bounds__(256)
void write_outg_kernel(const float* __restrict__ g, const float* __restrict__ m,
                       const float* __restrict__ Z, float* __restrict__ out)
{
    int i = blockIdx.x * 256 + threadIdx.x;
    if (i >= BB * VEXT) return;
    int b = i / VEXT;
    int j = i - b * VEXT;
    out[i] = (j < VV) ? expf(g[(size_t)b * VV + j] - m[b]) / Z[b] : 1e-4f;
}

// ---------------- prob_c + global sum ----------------
__global__ __launch_bounds__(256)
void probc_kernel(const float* __restrict__ c, const float* __restrict__ m,
                  const float* __restrict__ Z, float* __restrict__ pc,
                  float* __restrict__ pcsum)
{
    int b = blockIdx.x, t = threadIdx.x;
    float p = expf(c[b * SS + t] - m[b]) / Z[b];
    pc[b * SS + t] = p;
    __shared__ float sm[256];
    sm[t] = p; __syncthreads();
    for (int o = 128; o > 0; o >>= 1) { if (t < o) sm[t] += sm[t + o]; __syncthreads(); }
    if (t == 0) atomicAdd(pcsum, sm[0]);
}

__global__ void zero_pcsum_kernel(float* p) { *p = 0.f; }

// ---------------- scatter prob_c into out ----------------
__global__ __launch_bounds__(256)
void scatter_kernel(const int* __restrict__ eidx, const float* __restrict__ pc,
                    float* __restrict__ out)
{
    int i = blockIdx.x * 256 + threadIdx.x;
    if (i >= BB * SS) return;
    int b = i >> 8;
    atomicAdd(&out[b * VEXT + eidx[i]], pc[i]);
}

// ---------------- weighted_new ----------------
__global__ __launch_bounds__(512)
void weighted_kernel(const int* __restrict__ eidx, const int* __restrict__ iidx,
                     const float* __restrict__ pc, const float* __restrict__ enc,
                     const float* __restrict__ pcsum, float* __restrict__ outw)
{
    int b = blockIdx.x, t = threadIdx.x;
    __shared__ float coef[256];
    __shared__ int cnt;
    if (t == 0) cnt = 0;
    __syncthreads();
    if (t < 256) {
        int match = (eidx[b * SS + t] == iidx[b]);
        coef[t] = match ? pc[b * SS + t] : 0.f;
        if (match) atomicAdd(&cnt, 1);
    }
    __syncthreads();
    float scale = 1.f / (*pcsum);
    if (cnt > 1) scale /= (float)cnt;
    float acc = 0.f;
    const float* eb = enc + (size_t)b * SS * HH + t;
#pragma unroll 4
    for (int s = 0; s < SS; s++) acc += coef[s] * eb[s * HH];
    outw[b * HH + t] = acc * scale;
}

// =========================== launch ===========================
extern "C" void kernel_launch(void* const* d_in, const int* in_sizes, int n_in,
                              void* d_out, int out_size)
{
    const int*   input_idx   = (const int*)  d_in[0];
    const float* encoded     = (const float*)d_in[1];
    const int*   encoded_idx = (const int*)  d_in[2];
    const float* prev_state  = (const float*)d_in[3];
    const float* embed_table = (const float*)d_in[5];
    const float* Ws_w        = (const float*)d_in[6];
    const float* Ws_b        = (const float*)d_in[7];
    const float* gru_Wih     = (const float*)d_in[8];
    const float* gru_Whh     = (const float*)d_in[9];
    const float* gru_bih     = (const float*)d_in[10];
    const float* gru_bhh     = (const float*)d_in[11];
    const float* attn_W      = (const float*)d_in[12];
    const float* attn_b      = (const float*)d_in[13];
    const float* attn_v      = (const float*)d_in[14];
    const float* Wo_w        = (const float*)d_in[15];
    const float* Wo_b        = (const float*)d_in[16];
    const float* Wc_w        = (const float*)d_in[17];
    const float* Wc_b        = (const float*)d_in[18];

    float* out          = (float*)d_out;                 // [B, VEXT]
    float* out_state    = out + (size_t)BB * VEXT;       // [B, H]
    float* out_weighted = out_state + BB * HH;           // [B, H]

    float* sc = nullptr;
    cudaGetSymbolAddress((void**)&sc, g_scratch);
    float* xemb   = sc + OFF_XEMB;
    float* prev   = sc + OFF_PREV;
    float* gi     = sc + OFF_GI;
    float* gh     = sc + OFF_GH;
    float* state  = sc + OFF_STATE;
    float* satt   = sc + OFF_SATT;
    float* energy = sc + OFF_ENERGY;
    float* attnw  = sc + OFF_ATTNW;
    float* yv     = sc + OFF_Y;
    float* scoreg = sc + OFF_SCOREG;
    float* scorec = sc + OFF_SCOREC;
    float* probc  = sc + OFF_PROBC;
    float* mrow   = sc + OFF_M;
    float* zrow   = sc + OFF_Z;
    float* pcsum  = sc + OFF_PCSUM;

    // 0. zero the split-K accumulation buffers (prev..satt range)
    {
        int nz = OFF_SATT + BB * HH - OFF_PREV;
        zero_kernel<<<(nz + 255) / 256, 256>>>(prev, nz);
    }
    // 1. embed gather
    gather_embed<<<BB, EE>>>(input_idx, embed_table, xemb);
    // 2. prev = prev_state @ Ws_w^T + Ws_b
    gemm128_splitk<<<dim3(HH / 64, 4), 256>>>(prev_state, HH, Ws_w, HH, Ws_b,
                                              prev, HH, HH);
    // 3. gi = xemb @ Wih[:, :E]^T + bih
    gemm128_splitk<<<dim3(3 * HH / 64, 4), 256>>>(xemb, EE, gru_Wih, EE + HH,
                                                  gru_bih, gi, 3 * HH, EE);
    // 4. gh = prev @ Whh^T + bhh
    gemm128_splitk<<<dim3(3 * HH / 64, 4), 256>>>(prev, HH, gru_Whh, HH,
                                                  gru_bhh, gh, 3 * HH, HH);
    // 5. GRU
    gru_kernel<<<(BB * HH) / 256, 256>>>(gi, gh, prev, state, yv, out_state);
    // 6. satt = state @ attn_W[:, :H]^T + attn_b
    gemm128_splitk<<<dim3(HH / 64, 4), 256>>>(state, HH, attn_W, 2 * HH,
                                              attn_b, satt, HH, HH);
    // 7. energy
    fused_tanh_dot_v2<<<(BB * SS) / 128, 256>>>(encoded, attn_W + HH, 2 * HH,
                                                satt, 1, attn_v, 0, nullptr,
                                                HH, energy);
    // 8. softmax over S
    softmax_s_kernel<<<BB, SS>>>(energy, attnw);
    // 9. context
    context_kernel<<<BB, HH>>>(attnw, encoded, yv);
    // 10. score_g
    scoreg_v2<<<(VV + 63) / 64, 256>>>(yv, Wo_w, Wo_b, scoreg);
    // 11. score_c
    fused_tanh_dot_v2<<<(BB * SS) / 128, 256>>>(encoded, Wc_w, HH,
                                                Wc_b, 0, yv, 1, encoded_idx,
                                                2 * HH, scorec);
    // 12. softmax over concat(score_g, score_c)
    rowmaxsum_kernel<<<BB, 256>>>(scoreg, scorec, mrow, zrow);
    write_outg_kernel<<<(BB * VEXT + 255) / 256, 256>>>(scoreg, mrow, zrow, out);
    zero_pcsum_kernel<<<1, 1>>>(pcsum);
    probc_kernel<<<BB, SS>>>(scorec, mrow, zrow, probc, pcsum);
    // 13. scatter
    scatter_kernel<<<(BB * SS) / 256, 256>>>(encoded_idx, probc, out);
    // 14. weighted_new
    weighted_kernel<<<BB, HH>>>(encoded_idx, input_idx, probc, encoded,
                                pcsum, out_weighted);
}

// round 3
// speedup vs baseline: 1.7159x; 1.7159x over previous
#include <cuda_runtime.h>
#include <cuda_bf16.h>
#include <math.h>

#define VV 50000
#define EE 512
#define HH 512
#define BB 128
#define SS 256
#define OOV 12
#define VEXT (VV + OOV)   // 50012

// ---------------- scratch (device globals; no allocation) ----------------
#define OFF_XEMB   0                                 // B*E
#define OFF_PREV   (OFF_XEMB + BB*EE)                // B*H
#define OFF_GI     (OFF_PREV + BB*HH)                // B*3H
#define OFF_GH     (OFF_GI + BB*3*HH)
#define OFF_STATE  (OFF_GH + BB*3*HH)                // B*H
#define OFF_SATT   (OFF_STATE + BB*HH)               // B*H
#define OFF_ENERGY (OFF_SATT + BB*HH)                // B*S
#define OFF_ATTNW  (OFF_ENERGY + BB*SS)              // B*S
#define OFF_Y      (OFF_ATTNW + BB*SS)               // B*2H
#define OFF_SCOREG (OFF_Y + BB*2*HH)                 // B*V
#define OFF_SCOREC (OFF_SCOREG + (size_t)BB*VV)      // B*S
#define OFF_PROBC  (OFF_SCOREC + BB*SS)              // B*S
#define OFF_M      (OFF_PROBC + BB*SS)               // B
#define OFF_Z      (OFF_M + BB)                      // B
#define OFF_PCSUM  (OFF_Z + BB)                      // 1
#define SCRATCH_FLOATS (OFF_PCSUM + 64)

__device__ float g_scratch[SCRATCH_FLOATS];

// ---------------- f32x2 helpers ----------------
__device__ __forceinline__ void ffma2(unsigned long long &c,
                                      unsigned long long a,
                                      unsigned long long b) {
    asm("fma.rn.f32x2 %0, %1, %2, %0;" : "+l"(c) : "l"(a), "l"(b));
}
struct __align__(16) ull2 { unsigned long long x, y; };
__device__ __forceinline__ float f2lo(unsigned long long v) {
    return __uint_as_float((unsigned int)v);
}
__device__ __forceinline__ float f2hi(unsigned long long v) {
    return __uint_as_float((unsigned int)(v >> 32));
}
__device__ __forceinline__ unsigned long long dupf(float v) {
    unsigned int u = __float_as_uint(v);
    unsigned long long r;
    asm("mov.b64 %0, {%1, %1};" : "=l"(r) : "r"(u));
    return r;
}

// inner-loop body over one 16-k smem tile: acc[pair i (2 rows)][n j]
// Asm: [16][132] ([k][m], m = ty*8.. pairs), Wsm: [16][68] ([k][n])
#define K16_FFMA2_LOOP(acc, Asm, Wsm, ty, tx)                                 \
    _Pragma("unroll")                                                         \
    for (int kk = 0; kk < 16; kk++) {                                         \
        ull2 a01 = *(const ull2*)&Asm[kk][(ty) * 8];                          \
        ull2 a23 = *(const ull2*)&Asm[kk][(ty) * 8 + 4];                      \
        float4 wq = *(const float4*)&Wsm[kk][(tx) * 4];                       \
        unsigned long long w0 = dupf(wq.x), w1 = dupf(wq.y);                  \
        unsigned long long w2 = dupf(wq.z), w3 = dupf(wq.w);                  \
        ffma2(acc[0][0], a01.x, w0); ffma2(acc[0][1], a01.x, w1);             \
        ffma2(acc[0][2], a01.x, w2); ffma2(acc[0][3], a01.x, w3);             \
        ffma2(acc[1][0], a01.y, w0); ffma2(acc[1][1], a01.y, w1);             \
        ffma2(acc[1][2], a01.y, w2); ffma2(acc[1][3], a01.y, w3);             \
        ffma2(acc[2][0], a23.x, w0); ffma2(acc[2][1], a23.x, w1);             \
        ffma2(acc[2][2], a23.x, w2); ffma2(acc[2][3], a23.x, w3);             \
        ffma2(acc[3][0], a23.y, w0); ffma2(acc[3][1], a23.y, w1);             \
        ffma2(acc[3][2], a23.y, w2); ffma2(acc[3][3], a23.y, w3);             \
    }

// ---------------- zero scratch region ----------------
__global__ __launch_bounds__(256)
void zero_kernel(float* __restrict__ p, int n) {
    int i = blockIdx.x * 256 + threadIdx.x;
    if (i < n) p[i] = 0.f;
}

// ---------------- embed gather ----------------
__global__ __launch_bounds__(512)
void gather_embed(const int* __restrict__ idx, const float* __restrict__ tab,
                  float* __restrict__ x)
{
    int b = blockIdx.x, t = threadIdx.x;
    x[b * EE + t] = tab[(long)idx[b] * EE + t];
}

// ---------------- small GEMM (M=128), split-K, atomic accumulate ----------
__global__ __launch_bounds__(256)
void gemm128_splitk(const float* __restrict__ A, int lda,
                    const float* __restrict__ W, int ldw,
                    const float* __restrict__ bias,
                    float* __restrict__ C, int N, int Ktot)
{
    __shared__ float Asm[16][132];
    __shared__ float Wsm[16][68];
    const int tid = threadIdx.x;
    const int ty = tid >> 4, tx = tid & 15;
    const int n0 = blockIdx.x * 64;
    const int kl = Ktot / gridDim.y;
    const int ks = blockIdx.y * kl;
    const int am  = tid >> 2;
    const int akv = (tid & 3) << 2;

    unsigned long long acc[4][4];
#pragma unroll
    for (int i = 0; i < 4; i++)
#pragma unroll
        for (int j = 0; j < 4; j++) acc[i][j] = 0ull;

    for (int k0 = ks; k0 < ks + kl; k0 += 16) {
        __syncthreads();
#pragma unroll
        for (int r = 0; r < 2; r++) {
            int m = am + r * 64;
            float4 v = *(const float4*)&A[(size_t)m * lda + k0 + akv];
            Asm[akv+0][m] = v.x; Asm[akv+1][m] = v.y;
            Asm[akv+2][m] = v.z; Asm[akv+3][m] = v.w;
        }
        {
            float4 v = *(const float4*)&W[(size_t)(n0 + am) * ldw + k0 + akv];
            Wsm[akv+0][am] = v.x; Wsm[akv+1][am] = v.y;
            Wsm[akv+2][am] = v.z; Wsm[akv+3][am] = v.w;
        }
        __syncthreads();
        K16_FFMA2_LOOP(acc, Asm, Wsm, ty, tx)
    }
#pragma unroll
    for (int r2 = 0; r2 < 4; r2++) {
#pragma unroll
        for (int j = 0; j < 4; j++) {
            int n = n0 + tx * 4 + j;
            float bsum = (blockIdx.y == 0 && bias) ? bias[n] : 0.f;
            int m0 = ty * 8 + 2 * r2;
            atomicAdd(&C[(size_t)m0 * N + n],       f2lo(acc[r2][j]) + bsum);
            atomicAdd(&C[(size_t)(m0 + 1) * N + n], f2hi(acc[r2][j]) + bsum);
        }
    }
}

// ---------------- GRU elementwise ----------------
__global__ __launch_bounds__(256)
void gru_kernel(const float* __restrict__ gi, const float* __restrict__ gh,
                const float* __restrict__ prev,
                float* __restrict__ state, float* __restrict__ y,
                float* __restrict__ out_state)
{
    int i = blockIdx.x * 256 + threadIdx.x;
    int b = i / HH, h = i - b * HH;
    const float* gib = gi + b * 3 * HH;
    const float* ghb = gh + b * 3 * HH;
    float i_r = gib[h],          h_r = ghb[h];
    float i_z = gib[HH + h],     h_z = ghb[HH + h];
    float i_n = gib[2 * HH + h], h_n = ghb[2 * HH + h];
    float r = 1.f / (1.f + expf(-(i_r + h_r)));
    float z = 1.f / (1.f + expf(-(i_z + h_z)));
    float n = tanhf(i_n + r * h_n);
    float st = (1.f - z) * n + z * prev[i];
    state[i] = st;
    y[b * (2 * HH) + h] = st;
    out_state[i] = st;
}

// ---------------- fused: out[r] = sum_n tanh((A@W^T)[r,n] + add[n]) * wv[n] --
// 128 rows per block (same b), K = 512 fixed.
__global__ __launch_bounds__(256)
void fused_tanh_dot_v3(const float* __restrict__ A,
                       const float* __restrict__ W, int ldw,
                       const float* __restrict__ addg, int add_per_b,
                       const float* __restrict__ wvg, int wv_per_b,
                       const int* __restrict__ maskidx,
                       int Ntot, float* __restrict__ outv)
{
    const int row0 = blockIdx.x * 128;
    const int b = row0 >> 8;
    __shared__ float Asm[16][132];
    __shared__ float Wsm[16][68];
    __shared__ float addv[64];
    __shared__ float wvv[64];
    __shared__ float red[128][17];
    const int tid = threadIdx.x;
    const int ty = tid >> 4, tx = tid & 15;
    const int am  = tid >> 2;
    const int akv = (tid & 3) << 2;

    float partial[8];
#pragma unroll
    for (int i = 0; i < 8; i++) partial[i] = 0.f;

    for (int n0 = 0; n0 < Ntot; n0 += 64) {
        __syncthreads();
        if (tid < 64) {
            addv[tid] = add_per_b ? addg[b * Ntot + n0 + tid] : addg[n0 + tid];
            wvv[tid]  = wv_per_b  ? wvg[b * Ntot + n0 + tid]  : wvg[n0 + tid];
        }
        unsigned long long acc[4][4];
#pragma unroll
        for (int i = 0; i < 4; i++)
#pragma unroll
            for (int j = 0; j < 4; j++) acc[i][j] = 0ull;

        for (int k0 = 0; k0 < 512; k0 += 16) {
            __syncthreads();
#pragma unroll
            for (int r = 0; r < 2; r++) {
                int m = am + r * 64;
                float4 v = *(const float4*)&A[(size_t)(row0 + m) * 512 + k0 + akv];
                Asm[akv+0][m] = v.x; Asm[akv+1][m] = v.y;
                Asm[akv+2][m] = v.z; Asm[akv+3][m] = v.w;
            }
            {
                float4 v = *(const float4*)&W[(size_t)(n0 + am) * ldw + k0 + akv];
                Wsm[akv+0][am] = v.x; Wsm[akv+1][am] = v.y;
                Wsm[akv+2][am] = v.z; Wsm[akv+3][am] = v.w;
            }
            __syncthreads();
            K16_FFMA2_LOOP(acc, Asm, Wsm, ty, tx)
        }
        // epilogue: tanh + dot with wv (addv/wvv covered by in-loop barriers)
#pragma unroll
        for (int r2 = 0; r2 < 4; r2++) {
#pragma unroll
            for (int j = 0; j < 4; j++) {
                int n = tx * 4 + j;
                float ad = addv[n], wq = wvv[n];
                partial[2*r2]   += tanhf(f2lo(acc[r2][j]) + ad) * wq;
                partial[2*r2+1] += tanhf(f2hi(acc[r2][j]) + ad) * wq;
            }
        }
    }
    __syncthreads();
#pragma unroll
    for (int i = 0; i < 8; i++) red[ty * 8 + i][tx] = partial[i];
    __syncthreads();
    if (tid < 128) {
        float s = 0.f;
#pragma unroll
        for (int j = 0; j < 16; j++) s += red[tid][j];
        int r = row0 + tid;
        if (maskidx && maskidx[r] == 0) s -= 1000.f;
        outv[r] = s;
    }
}

// ---------------- score_g: [128,50000] = y[128,1024] @ Wo^T + Wo_b ----------
__global__ __launch_bounds__(256)
void scoreg_v3(const float* __restrict__ y, const float* __restrict__ Wo,
               const float* __restrict__ Wob, float* __restrict__ outg)
{
    __shared__ float Asm[16][132];
    __shared__ float Wsm[16][68];
    const int tid = threadIdx.x;
    const int ty = tid >> 4, tx = tid & 15;
    const int n0 = blockIdx.x * 64;
    const int am  = tid >> 2;
    const int akv = (tid & 3) << 2;

    unsigned long long acc[4][4];
#pragma unroll
    for (int i = 0; i < 4; i++)
#pragma unroll
        for (int j = 0; j < 4; j++) acc[i][j] = 0ull;

    for (int k0 = 0; k0 < 1024; k0 += 16) {
        __syncthreads();
#pragma unroll
        for (int r = 0; r < 2; r++) {
            int m = am + r * 64;
            float4 v = *(const float4*)&y[(size_t)m * 1024 + k0 + akv];
            Asm[akv+0][m] = v.x; Asm[akv+1][m] = v.y;
            Asm[akv+2][m] = v.z; Asm[akv+3][m] = v.w;
        }
        {
            int ng = n0 + am;
            float4 v = make_float4(0.f, 0.f, 0.f, 0.f);
            if (ng < VV) v = *(const float4*)&Wo[(size_t)ng * 1024 + k0 + akv];
            Wsm[akv+0][am] = v.x; Wsm[akv+1][am] = v.y;
            Wsm[akv+2][am] = v.z; Wsm[akv+3][am] = v.w;
        }
        __syncthreads();
        K16_FFMA2_LOOP(acc, Asm, Wsm, ty, tx)
    }
    int n = n0 + tx * 4;
    if (n < VV) {   // VV % 4 == 0, so float4 at n is all-in or all-out
        float4 bv = *(const float4*)&Wob[n];
#pragma unroll
        for (int r2 = 0; r2 < 4; r2++) {
            int m0 = ty * 8 + 2 * r2;
            float4 lo = make_float4(f2lo(acc[r2][0]) + bv.x, f2lo(acc[r2][1]) + bv.y,
                                    f2lo(acc[r2][2]) + bv.z, f2lo(acc[r2][3]) + bv.w);
            float4 hi = make_float4(f2hi(acc[r2][0]) + bv.x, f2hi(acc[r2][1]) + bv.y,
                                    f2hi(acc[r2][2]) + bv.z, f2hi(acc[r2][3]) + bv.w);
            *(float4*)&outg[(size_t)m0 * VV + n]       = lo;
            *(float4*)&outg[(size_t)(m0 + 1) * VV + n] = hi;
        }
    }
}

// ---------------- attn softmax over S ----------------
__global__ __launch_bounds__(256)
void softmax_s_kernel(const float* __restrict__ e, float* __restrict__ w)
{
    int b = blockIdx.x, t = threadIdx.x;
    __shared__ float sm[256];
    __shared__ float bc;
    float x = e[b * SS + t];
    sm[t] = x; __syncthreads();
    for (int o = 128; o > 0; o >>= 1) { if (t < o) sm[t] = fmaxf(sm[t], sm[t + o]); __syncthreads(); }
    if (t == 0) bc = sm[0];
    __syncthreads();
    float ex = expf(x - bc);
    __syncthreads();
    sm[t] = ex; __syncthreads();
    for (int o = 128; o > 0; o >>= 1) { if (t < o) sm[t] += sm[t + o]; __syncthreads(); }
    if (t == 0) bc = sm[0];
    __syncthreads();
    w[b * SS + t] = ex / bc;
}

// ---------------- context = sum_s attnw * encoded (into y[:,H:]) -----------
__global__ __launch_bounds__(512)
void context_kernel(const float* __restrict__ aw, const float* __restrict__ enc,
                    float* __restrict__ y)
{
    int b = blockIdx.x, h = threadIdx.x;
    __shared__ float c[256];
    if (h < 256) c[h] = aw[b * SS + h];
    __syncthreads();
    float acc = 0.f;
    const float* eb = enc + (size_t)b * SS * HH + h;
#pragma unroll 4
    for (int s = 0; s < SS; s++) acc += c[s] * eb[s * HH];
    y[b * (2 * HH) + HH + h] = acc;
}

// ---------------- online row max + sumexp over concat(score_g, score_c) ----
__global__ __launch_bounds__(256)
void rowmaxsum_kernel(const float* __restrict__ g, const float* __restrict__ c,
                      float* __restrict__ mout, float* __restrict__ zout)
{
    int b = blockIdx.x, t = threadIdx.x;
    float m = -1e30f, z = 0.f;
    const float* gb = g + (size_t)b * VV;
    for (int j = t; j < VV; j += 256) {
        float x = gb[j];
        if (x > m) { z = z * expf(m - x) + 1.f; m = x; }
        else z += expf(x - m);
    }
    {
        float x = c[b * SS + t];
        if (x > m) { z = z * expf(m - x) + 1.f; m = x; }
        else z += expf(x - m);
    }
    __shared__ float sm[256], sz[256];
    sm[t] = m; sz[t] = z; __syncthreads();
    for (int o = 128; o > 0; o >>= 1) {
        if (t < o) {
            float m1 = sm[t], m2 = sm[t + o];
            float M = fmaxf(m1, m2);
            sz[t] = sz[t] * expf(m1 - M) + sz[t + o] * expf(m2 - M);
            sm[t] = M;
        }
        __syncthreads();
    }
    if (t == 0) { mout[b] = sm[0]; zout[b] = sz[0]; }
}

// ---------------- write prob_g_ext into out ----------------
__global__ __launch_bounds__(256)
void write_outg_kernel(const float* __restrict__ g, const float* __restrict__ m,
                       const float* __restrict__ Z, float* __restrict__ out)
{
    int i = blockIdx.x * 256 + threadIdx.x;
    if (i >= BB * VEXT) return;
    int b = i / VEXT;
    int j = i - b * VEXT;
    out[i] = (j < VV) ? expf(g[(size_t)b * VV + j] - m[b]) / Z[b] : 1e-4f;
}

// ---------------- prob_c + global sum ----------------
__global__ __launch_bounds__(256)
void probc_kernel(const float* __restrict__ c, const float* __restrict__ m,
                  const float* __restrict__ Z, float* __restrict__ pc,
                  float* __restrict__ pcsum)
{
    int b = blockIdx.x, t = threadIdx.x;
    float p = expf(c[b * SS + t] - m[b]) / Z[b];
    pc[b * SS + t] = p;
    __shared__ float sm[256];
    sm[t] = p; __syncthreads();
    for (int o = 128; o > 0; o >>= 1) { if (t < o) sm[t] += sm[t + o]; __syncthreads(); }
    if (t == 0) atomicAdd(pcsum, sm[0]);
}

__global__ void zero_pcsum_kernel(float* p) { *p = 0.f; }

// ---------------- scatter prob_c into out ----------------
__global__ __launch_bounds__(256)
void scatter_kernel(const int* __restrict__ eidx, const float* __restrict__ pc,
                    float* __restrict__ out)
{
    int i = blockIdx.x * 256 + threadIdx.x;
    if (i >= BB * SS) return;
    int b = i >> 8;
    atomicAdd(&out[b * VEXT + eidx[i]], pc[i]);
}

// ---------------- weighted_new ----------------
__global__ __launch_bounds__(512)
void weighted_kernel(const int* __restrict__ eidx, const int* __restrict__ iidx,
                     const float* __restrict__ pc, const float* __restrict__ enc,
                     const float* __restrict__ pcsum, float* __restrict__ outw)
{
    int b = blockIdx.x, t = threadIdx.x;
    __shared__ float coef[256];
    __shared__ int cnt;
    if (t == 0) cnt = 0;
    __syncthreads();
    if (t < 256) {
        int match = (eidx[b * SS + t] == iidx[b]);
        coef[t] = match ? pc[b * SS + t] : 0.f;
        if (match) atomicAdd(&cnt, 1);
    }
    __syncthreads();
    float scale = 1.f / (*pcsum);
    if (cnt > 1) scale /= (float)cnt;
    float acc = 0.f;
    const float* eb = enc + (size_t)b * SS * HH + t;
#pragma unroll 4
    for (int s = 0; s < SS; s++) acc += coef[s] * eb[s * HH];
    outw[b * HH + t] = acc * scale;
}

// =========================== launch ===========================
extern "C" void kernel_launch(void* const* d_in, const int* in_sizes, int n_in,
                              void* d_out, int out_size)
{
    const int*   input_idx   = (const int*)  d_in[0];
    const float* encoded     = (const float*)d_in[1];
    const int*   encoded_idx = (const int*)  d_in[2];
    const float* prev_state  = (const float*)d_in[3];
    const float* embed_table = (const float*)d_in[5];
    const float* Ws_w        = (const float*)d_in[6];
    const float* Ws_b        = (const float*)d_in[7];
    const float* gru_Wih     = (const float*)d_in[8];
    const float* gru_Whh     = (const float*)d_in[9];
    const float* gru_bih     = (const float*)d_in[10];
    const float* gru_bhh     = (const float*)d_in[11];
    const float* attn_W      = (const float*)d_in[12];
    const float* attn_b      = (const float*)d_in[13];
    const float* attn_v      = (const float*)d_in[14];
    const float* Wo_w        = (const float*)d_in[15];
    const float* Wo_b        = (const float*)d_in[16];
    const float* Wc_w        = (const float*)d_in[17];
    const float* Wc_b        = (const float*)d_in[18];

    float* out          = (float*)d_out;                 // [B, VEXT]
    float* out_state    = out + (size_t)BB * VEXT;       // [B, H]
    float* out_weighted = out_state + BB * HH;           // [B, H]

    float* sc = nullptr;
    cudaGetSymbolAddress((void**)&sc, g_scratch);
    float* xemb   = sc + OFF_XEMB;
    float* prev   = sc + OFF_PREV;
    float* gi     = sc + OFF_GI;
    float* gh     = sc + OFF_GH;
    float* state  = sc + OFF_STATE;
    float* satt   = sc + OFF_SATT;
    float* energy = sc + OFF_ENERGY;
    float* attnw  = sc + OFF_ATTNW;
    float* yv     = sc + OFF_Y;
    float* scoreg = sc + OFF_SCOREG;
    float* scorec = sc + OFF_SCOREC;
    float* probc  = sc + OFF_PROBC;
    float* mrow   = sc + OFF_M;
    float* zrow   = sc + OFF_Z;
    float* pcsum  = sc + OFF_PCSUM;

    // 0. zero split-K accumulation range (prev..satt)
    {
        int nz = OFF_SATT + BB * HH - OFF_PREV;
        zero_kernel<<<(nz + 255) / 256, 256>>>(prev, nz);
    }
    // 1. embed gather
    gather_embed<<<BB, EE>>>(input_idx, embed_table, xemb);
    // 2. prev = prev_state @ Ws_w^T + Ws_b
    gemm128_splitk<<<dim3(HH / 64, 4), 256>>>(prev_state, HH, Ws_w, HH, Ws_b,
                                              prev, HH, HH);
    // 3. gi = xemb @ Wih[:, :E]^T + bih
    gemm128_splitk<<<dim3(3 * HH / 64, 4), 256>>>(xemb, EE, gru_Wih, EE + HH,
                                                  gru_bih, gi, 3 * HH, EE);
    // 4. gh = prev @ Whh^T + bhh
    gemm128_splitk<<<dim3(3 * HH / 64, 4), 256>>>(prev, HH, gru_Whh, HH,
                                                  gru_bhh, gh, 3 * HH, HH);
    // 5. GRU
    gru_kernel<<<(BB * HH) / 256, 256>>>(gi, gh, prev, state, yv, out_state);
    // 6. satt = state @ attn_W[:, :H]^T + attn_b
    gemm128_splitk<<<dim3(HH / 64, 4), 256>>>(state, HH, attn_W, 2 * HH,
                                              attn_b, satt, HH, HH);
    // 7. energy
    fused_tanh_dot_v3<<<(BB * SS) / 128, 256>>>(encoded, attn_W + HH, 2 * HH,
                                                satt, 1, attn_v, 0, nullptr,
                                                HH, energy);
    // 8. softmax over S
    softmax_s_kernel<<<BB, SS>>>(energy, attnw);
    // 9. context
    context_kernel<<<BB, HH>>>(attnw, encoded, yv);
    // 10. score_g
    scoreg_v3<<<(VV + 63) / 64, 256>>>(yv, Wo_w, Wo_b, scoreg);
    // 11. score_c
    fused_tanh_dot_v3<<<(BB * SS) / 128, 256>>>(encoded, Wc_w, HH,
                                                Wc_b, 0, yv, 1, encoded_idx,
                                                2 * HH, scorec);
    // 12. softmax over concat(score_g, score_c)
    rowmaxsum_kernel<<<BB, 256>>>(scoreg, scorec, mrow, zrow);
    write_outg_kernel<<<(BB * VEXT + 255) / 256, 256>>>(scoreg, mrow, zrow, out);
    zero_pcsum_kernel<<<1, 1>>>(pcsum);
    probc_kernel<<<BB, SS>>>(scorec, mrow, zrow, probc, pcsum);
    // 13. scatter
    scatter_kernel<<<(BB * SS) / 256, 256>>>(encoded_idx, probc, out);
    // 14. weighted_new
    weighted_kernel<<<BB, HH>>>(encoded_idx, input_idx, probc, encoded,
                                pcsum, out_weighted);
}

// round 6
// speedup vs baseline: 3.8916x; 2.2679x over previous
#include <cuda_runtime.h>
#include <cuda_fp16.h>
#include <math.h>
#include <stdint.h>

#define VV 50000
#define EE 512
#define HH 512
#define BB 128
#define SS 256
#define OOV 12
#define VEXT (VV + OOV)   // 50012

// ---------------- fp32 scratch ----------------
#define OFF_XEMB   0
#define OFF_PREV   (OFF_XEMB + BB*EE)
#define OFF_GI     (OFF_PREV + BB*HH)
#define OFF_GH     (OFF_GI + BB*3*HH)
#define OFF_STATE  (OFF_GH + BB*3*HH)
#define OFF_SATT   (OFF_STATE + BB*HH)
#define OFF_ENERGY (OFF_SATT + BB*HH)
#define OFF_ATTNW  (OFF_ENERGY + BB*SS)
#define OFF_Y      (OFF_ATTNW + BB*SS)
#define OFF_SCOREG (OFF_Y + BB*2*HH)
#define OFF_SCOREC (OFF_SCOREG + (size_t)BB*VV)
#define OFF_PROBC  (OFF_SCOREC + BB*SS)
#define OFF_M      (OFF_PROBC + BB*SS)
#define OFF_Z      (OFF_M + BB)
#define OFF_PCSUM  (OFF_Z + BB)
#define SCRATCH_FLOATS (OFF_PCSUM + 64)

__device__ float g_scratch[SCRATCH_FLOATS];

// ---------------- fp16 buffers ----------------
__device__ __half g_enc_h[(size_t)32768 * 1024];  // A split [hi|lo], K'=1024
__device__ __half g_y_h  [(size_t)128   * 2048];  // A split, K'=2048
__device__ __half g_wo_h [(size_t)50000 * 1024];  // B fp16
__device__ __half g_wc_h [(size_t)1024  * 512];
__device__ __half g_aw2_h[(size_t)512   * 512];

// ---------------- helpers ----------------
__device__ __forceinline__ uint32_t smem_u32(const void* p) {
    uint32_t a;
    asm("{ .reg .u64 t; cvta.to.shared.u64 t, %1; cvt.u32.u64 %0, t; }"
        : "=r"(a) : "l"(p));
    return a;
}
static __device__ __forceinline__ uint32_t SWZ(uint32_t o) {
    return o ^ ((o >> 3) & 0x70u);
}
__device__ __forceinline__ void cpa16(uint32_t dst, const void* src, int srcsize) {
    asm volatile("cp.async.cg.shared.global [%0], [%1], 16, %2;"
                 :: "r"(dst), "l"(src), "r"(srcsize) : "memory");
}
__device__ __forceinline__ void cpa_commit() {
    asm volatile("cp.async.commit_group;" ::: "memory");
}
__device__ __forceinline__ void cpa_wait1() {
    asm volatile("cp.async.wait_group 1;" ::: "memory");
}
__device__ __forceinline__ void cpa_wait0() {
    asm volatile("cp.async.wait_group 0;" ::: "memory");
}
__device__ __forceinline__ void ldm_x4(uint32_t& r0, uint32_t& r1,
                                       uint32_t& r2, uint32_t& r3, uint32_t a) {
    asm volatile("ldmatrix.sync.aligned.m8n8.x4.shared.b16 {%0,%1,%2,%3}, [%4];"
                 : "=r"(r0), "=r"(r1), "=r"(r2), "=r"(r3) : "r"(a));
}
__device__ __forceinline__ void mma16816(float& c0, float& c1, float& c2, float& c3,
                                         uint32_t a0, uint32_t a1, uint32_t a2,
                                         uint32_t a3, uint32_t b0, uint32_t b1) {
    asm volatile("mma.sync.aligned.m16n8k16.row.col.f32.f16.f16.f32 "
                 "{%0,%1,%2,%3}, {%4,%5,%6,%7}, {%8,%9}, {%0,%1,%2,%3};"
                 : "+f"(c0), "+f"(c1), "+f"(c2), "+f"(c3)
                 : "r"(a0), "r"(a1), "r"(a2), "r"(a3), "r"(b0), "r"(b1));
}

// ================= HMMA GEMM =================
// Block tile 128(rows) x 128(cols), k-chunk 64, cp.async double buffer.
// A: fp16 [rowsTot x AldK]  (AldK = 2K: [hi|lo]).  B: fp16 [Nrows x K], k-major.
// Effective: D[m][n] = sum_{k'<AldK} A[m][k'] * B[n][k' mod K].
// mode 0: outS[(row0+m)*ldout + n] = D + add_s[n]   (add_s <- bias)
// mode 1: atomicAdd(outv[row0+m], sum_n tanh(D + add_s[n]) * wv_s[n])
#define HS_A(par)  ((par) * 16384)
#define HS_B(par)  (32768 + (par) * 16384)
#define HS_ADD     65536
#define HS_WV      66048
#define H_SMEM_DYN (66560 + 1024)

__global__ __launch_bounds__(256)
void hmma_gemm(const __half* __restrict__ A, int AldK,
               const __half* __restrict__ B, int K, int Nrows,
               int mode,
               const float* __restrict__ biasOrAdd, int add_per_b, int Ntot,
               const float* __restrict__ wvg, int wv_per_b,
               float* __restrict__ outS, int ldout,
               float* __restrict__ outv)
{
    extern __shared__ char smem_raw[];
    char* smem = (char*)(((uintptr_t)smem_raw + 1023) & ~(uintptr_t)1023);
    const uint32_t sb = smem_u32(smem);
    const int tid = threadIdx.x, wid = tid >> 5, lid = tid & 31;
    const int row0 = blockIdx.x * 128;
    const int n0   = blockIdx.y * 128;
    const int b    = row0 >> 8;
    const int wm0  = (wid >> 2) * 64;   // warp row origin (0 or 64)
    const int wn0  = (wid & 3) * 32;    // warp col origin

    float* add_s = (float*)(smem + HS_ADD);
    float* wv_s  = (float*)(smem + HS_WV);
    if (tid < 128) {
        int gn = n0 + tid;
        if (mode == 0) {
            add_s[tid] = (gn < Nrows) ? biasOrAdd[gn] : 0.f;
        } else {
            add_s[tid] = add_per_b ? biasOrAdd[(size_t)b * Ntot + gn]
                                   : biasOrAdd[gn];
            wv_s[tid]  = wv_per_b ? wvg[(size_t)b * Ntot + gn] : wvg[gn];
        }
    }

    const int nc = AldK >> 6;
    const int lr = tid >> 3;           // loader row 0..31 (x4 iters -> 128)
    const int lu = tid & 7;            // 16B unit 0..7 (full 128B row)

    // ---- chunk issuer: full 128 rows x 128 bytes per matrix ----
    auto issue = [&](int c, int par) {
        int kA = c * 64;
        int kB = (kA >= K) ? kA - K : kA;
#pragma unroll
        for (int it = 0; it < 4; it++) {
            int r = lr + it * 32;
            cpa16(sb + HS_A(par) + SWZ((uint32_t)(r * 128 + lu * 16)),
                  &A[(size_t)(row0 + r) * AldK + kA + lu * 8], 16);
            int gr = n0 + r;
            int ok = (gr < Nrows) ? 16 : 0;
            int grc = (gr < Nrows) ? gr : 0;
            cpa16(sb + HS_B(par) + SWZ((uint32_t)(r * 128 + lu * 16)),
                  &B[(size_t)grc * K + kB + lu * 8], ok);
        }
        cpa_commit();
    };

    float cacc[4][4][4];
#pragma unroll
    for (int mi = 0; mi < 4; mi++)
#pragma unroll
        for (int nj = 0; nj < 4; nj++)
#pragma unroll
            for (int f = 0; f < 4; f++) cacc[mi][nj][f] = 0.f;

    // ldmatrix lane address components (constant over chunks)
    const int a_row = wm0 + (lid & 15);
    const int a_csel = ((lid >> 4) & 1) * 16;
    const int b_rowo = (lid & 7) + ((lid >> 4) & 1) * 8;
    const int b_csel = ((lid >> 3) & 1) * 16;

    issue(0, 0);
    for (int c = 0; c < nc; c++) {
        const int par = c & 1;
        if (c + 1 < nc) { issue(c + 1, par ^ 1); cpa_wait1(); }
        else            { cpa_wait0(); }
        __syncthreads();

        const uint32_t ab = sb + HS_A(par);
        const uint32_t bb = sb + HS_B(par);
#pragma unroll
        for (int k16 = 0; k16 < 4; k16++) {
            uint32_t a[4][4];
#pragma unroll
            for (int mi = 0; mi < 4; mi++) {
                uint32_t addr = ab + SWZ((uint32_t)((a_row + mi * 16) * 128 +
                                                    k16 * 32 + a_csel));
                ldm_x4(a[mi][0], a[mi][1], a[mi][2], a[mi][3], addr);
            }
            uint32_t bf[4][2];
#pragma unroll
            for (int nj = 0; nj < 2; nj++) {
                uint32_t addr = bb + SWZ((uint32_t)((wn0 + nj * 16 + b_rowo) * 128 +
                                                    k16 * 32 + b_csel));
                ldm_x4(bf[2 * nj][0], bf[2 * nj][1],
                       bf[2 * nj + 1][0], bf[2 * nj + 1][1], addr);
            }
#pragma unroll
            for (int mi = 0; mi < 4; mi++)
#pragma unroll
                for (int nj = 0; nj < 4; nj++)
                    mma16816(cacc[mi][nj][0], cacc[mi][nj][1],
                             cacc[mi][nj][2], cacc[mi][nj][3],
                             a[mi][0], a[mi][1], a[mi][2], a[mi][3],
                             bf[nj][0], bf[nj][1]);
        }
        __syncthreads();
    }

    // ---- epilogue ----
    const int rA = wm0 + (lid >> 2);          // local row (+ mi*16, +8)
    const int lcol = wn0 + 2 * (lid & 3);     // local col base (+ nj*8)
    if (mode == 0) {
#pragma unroll
        for (int mi = 0; mi < 4; mi++) {
#pragma unroll
            for (int nj = 0; nj < 4; nj++) {
                int lc = lcol + nj * 8;
                int n = n0 + lc;
                if (n < Nrows) {
                    int r0r = row0 + rA + mi * 16;
                    float2 v0 = make_float2(cacc[mi][nj][0] + add_s[lc],
                                            cacc[mi][nj][1] + add_s[lc + 1]);
                    float2 v1 = make_float2(cacc[mi][nj][2] + add_s[lc],
                                            cacc[mi][nj][3] + add_s[lc + 1]);
                    *(float2*)&outS[(size_t)r0r * ldout + n] = v0;
                    *(float2*)&outS[(size_t)(r0r + 8) * ldout + n] = v1;
                }
            }
        }
    } else {
#pragma unroll
        for (int mi = 0; mi < 4; mi++) {
            float p0 = 0.f, p1 = 0.f;
#pragma unroll
            for (int nj = 0; nj < 4; nj++) {
                int lc = lcol + nj * 8;
                float ad0 = add_s[lc], ad1 = add_s[lc + 1];
                float w0 = wv_s[lc],  w1 = wv_s[lc + 1];
                p0 += tanhf(cacc[mi][nj][0] + ad0) * w0
                    + tanhf(cacc[mi][nj][1] + ad1) * w1;
                p1 += tanhf(cacc[mi][nj][2] + ad0) * w0
                    + tanhf(cacc[mi][nj][3] + ad1) * w1;
            }
            p0 += __shfl_xor_sync(0xffffffffu, p0, 1);
            p0 += __shfl_xor_sync(0xffffffffu, p0, 2);
            p1 += __shfl_xor_sync(0xffffffffu, p1, 1);
            p1 += __shfl_xor_sync(0xffffffffu, p1, 2);
            if ((lid & 3) == 0) {
                atomicAdd(&outv[row0 + rA + mi * 16], p0);
                atomicAdd(&outv[row0 + rA + mi * 16 + 8], p1);
            }
        }
    }
}

// ================= fp16 conversion kernels =================
__global__ __launch_bounds__(256)
void splitA_h(const float* __restrict__ in, int ldin,
              __half* __restrict__ out, int K, long total)
{
    long i = (long)blockIdx.x * 256 + threadIdx.x;
    if (i >= total) return;
    long r = i / K; int k = (int)(i - r * K);
    float x = in[r * ldin + k];
    __half hi = __float2half(x);
    __half lo = __float2half(x - __half2float(hi));
    out[r * 2 * K + k] = hi;
    out[r * 2 * K + K + k] = lo;
}
__global__ __launch_bounds__(256)
void convB_h(const float* __restrict__ in, int ldin, int coloff,
             __half* __restrict__ out, int K, long total)
{
    long i = (long)blockIdx.x * 256 + threadIdx.x;
    if (i >= total) return;
    long r = i / K; int k = (int)(i - r * K);
    out[r * K + k] = __float2half(in[r * ldin + coloff + k]);
}

// ================= FFMA2 small GEMM chain (from R3) =================
__device__ __forceinline__ void ffma2(unsigned long long &c,
                                      unsigned long long a,
                                      unsigned long long b) {
    asm("fma.rn.f32x2 %0, %1, %2, %0;" : "+l"(c) : "l"(a), "l"(b));
}
struct __align__(16) ull2 { unsigned long long x, y; };
__device__ __forceinline__ float f2lo(unsigned long long v) {
    return __uint_as_float((unsigned int)v);
}
__device__ __forceinline__ float f2hi(unsigned long long v) {
    return __uint_as_float((unsigned int)(v >> 32));
}
__device__ __forceinline__ unsigned long long dupf(float v) {
    unsigned int u = __float_as_uint(v);
    unsigned long long r;
    asm("mov.b64 %0, {%1, %1};" : "=l"(r) : "r"(u));
    return r;
}
#define K16_FFMA2_LOOP(acc, Asm, Wsm, ty, tx)                                 \
    _Pragma("unroll")                                                         \
    for (int kk = 0; kk < 16; kk++) {                                         \
        ull2 a01 = *(const ull2*)&Asm[kk][(ty) * 8];                          \
        ull2 a23 = *(const ull2*)&Asm[kk][(ty) * 8 + 4];                      \
        float4 wq = *(const float4*)&Wsm[kk][(tx) * 4];                       \
        unsigned long long w0 = dupf(wq.x), w1 = dupf(wq.y);                  \
        unsigned long long w2 = dupf(wq.z), w3 = dupf(wq.w);                  \
        ffma2(acc[0][0], a01.x, w0); ffma2(acc[0][1], a01.x, w1);             \
        ffma2(acc[0][2], a01.x, w2); ffma2(acc[0][3], a01.x, w3);             \
        ffma2(acc[1][0], a01.y, w0); ffma2(acc[1][1], a01.y, w1);             \
        ffma2(acc[1][2], a01.y, w2); ffma2(acc[1][3], a01.y, w3);             \
        ffma2(acc[2][0], a23.x, w0); ffma2(acc[2][1], a23.x, w1);             \
        ffma2(acc[2][2], a23.x, w2); ffma2(acc[2][3], a23.x, w3);             \
        ffma2(acc[3][0], a23.y, w0); ffma2(acc[3][1], a23.y, w1);             \
        ffma2(acc[3][2], a23.y, w2); ffma2(acc[3][3], a23.y, w3);             \
    }

__global__ __launch_bounds__(256)
void zero_kernel(float* __restrict__ p, int n) {
    int i = blockIdx.x * 256 + threadIdx.x;
    if (i < n) p[i] = 0.f;
}

__global__ __launch_bounds__(512)
void gather_embed(const int* __restrict__ idx, const float* __restrict__ tab,
                  float* __restrict__ x)
{
    int b = blockIdx.x, t = threadIdx.x;
    x[b * EE + t] = tab[(long)idx[b] * EE + t];
}

__global__ __launch_bounds__(256)
void gemm128_splitk(const float* __restrict__ A, int lda,
                    const float* __restrict__ W, int ldw,
                    const float* __restrict__ bias,
                    float* __restrict__ C, int N, int Ktot)
{
    __shared__ float Asm[16][132];
    __shared__ float Wsm[16][68];
    const int tid = threadIdx.x;
    const int ty = tid >> 4, tx = tid & 15;
    const int n0 = blockIdx.x * 64;
    const int kl = Ktot / gridDim.y;
    const int ks = blockIdx.y * kl;
    const int am  = tid >> 2;
    const int akv = (tid & 3) << 2;

    unsigned long long acc[4][4];
#pragma unroll
    for (int i = 0; i < 4; i++)
#pragma unroll
        for (int j = 0; j < 4; j++) acc[i][j] = 0ull;

    for (int k0 = ks; k0 < ks + kl; k0 += 16) {
        __syncthreads();
#pragma unroll
        for (int r = 0; r < 2; r++) {
            int m = am + r * 64;
            float4 v = *(const float4*)&A[(size_t)m * lda + k0 + akv];
            Asm[akv+0][m] = v.x; Asm[akv+1][m] = v.y;
            Asm[akv+2][m] = v.z; Asm[akv+3][m] = v.w;
        }
        {
            float4 v = *(const float4*)&W[(size_t)(n0 + am) * ldw + k0 + akv];
            Wsm[akv+0][am] = v.x; Wsm[akv+1][am] = v.y;
            Wsm[akv+2][am] = v.z; Wsm[akv+3][am] = v.w;
        }
        __syncthreads();
        K16_FFMA2_LOOP(acc, Asm, Wsm, ty, tx)
    }
#pragma unroll
    for (int r2 = 0; r2 < 4; r2++) {
#pragma unroll
        for (int j = 0; j < 4; j++) {
            int n = n0 + tx * 4 + j;
            float bsum = (blockIdx.y == 0 && bias) ? bias[n] : 0.f;
            int m0 = ty * 8 + 2 * r2;
            atomicAdd(&C[(size_t)m0 * N + n],       f2lo(acc[r2][j]) + bsum);
            atomicAdd(&C[(size_t)(m0 + 1) * N + n], f2hi(acc[r2][j]) + bsum);
        }
    }
}

__global__ __launch_bounds__(256)
void gru_kernel(const float* __restrict__ gi, const float* __restrict__ gh,
                const float* __restrict__ prev,
                float* __restrict__ state, float* __restrict__ y,
                float* __restrict__ out_state)
{
    int i = blockIdx.x * 256 + threadIdx.x;
    int b = i / HH, h = i - b * HH;
    const float* gib = gi + b * 3 * HH;
    const float* ghb = gh + b * 3 * HH;
    float i_r = gib[h],          h_r = ghb[h];
    float i_z = gib[HH + h],     h_z = ghb[HH + h];
    float i_n = gib[2 * HH + h], h_n = ghb[2 * HH + h];
    float r = 1.f / (1.f + expf(-(i_r + h_r)));
    float z = 1.f / (1.f + expf(-(i_z + h_z)));
    float n = tanhf(i_n + r * h_n);
    float st = (1.f - z) * n + z * prev[i];
    state[i] = st;
    y[b * (2 * HH) + h] = st;
    out_state[i] = st;
}

__global__ __launch_bounds__(256)
void softmax_s_kernel(const float* __restrict__ e, float* __restrict__ w)
{
    int b = blockIdx.x, t = threadIdx.x;
    __shared__ float sm[256];
    __shared__ float bc;
    float x = e[b * SS + t];
    sm[t] = x; __syncthreads();
    for (int o = 128; o > 0; o >>= 1) { if (t < o) sm[t] = fmaxf(sm[t], sm[t + o]); __syncthreads(); }
    if (t == 0) bc = sm[0];
    __syncthreads();
    float ex = expf(x - bc);
    __syncthreads();
    sm[t] = ex; __syncthreads();
    for (int o = 128; o > 0; o >>= 1) { if (t < o) sm[t] += sm[t + o]; __syncthreads(); }
    if (t == 0) bc = sm[0];
    __syncthreads();
    w[b * SS + t] = ex / bc;
}

__global__ __launch_bounds__(512)
void context_kernel(const float* __restrict__ aw, const float* __restrict__ enc,
                    float* __restrict__ y)
{
    int b = blockIdx.x, h = threadIdx.x;
    __shared__ float c[256];
    if (h < 256) c[h] = aw[b * SS + h];
    __syncthreads();
    float acc = 0.f;
    const float* eb = enc + (size_t)b * SS * HH + h;
#pragma unroll 4
    for (int s = 0; s < SS; s++) acc += c[s] * eb[s * HH];
    y[b * (2 * HH) + HH + h] = acc;
}

__global__ __launch_bounds__(256)
void mask_kernel(const int* __restrict__ eidx, float* __restrict__ scorec)
{
    int i = blockIdx.x * 256 + threadIdx.x;
    if (i < BB * SS && eidx[i] == 0) scorec[i] -= 1000.f;
}

__global__ __launch_bounds__(256)
void rowmaxsum_kernel(const float* __restrict__ g, const float* __restrict__ c,
                      float* __restrict__ mout, float* __restrict__ zout)
{
    int b = blockIdx.x, t = threadIdx.x;
    float m = -1e30f, z = 0.f;
    const float* gb = g + (size_t)b * VV;
    for (int j = t; j < VV; j += 256) {
        float x = gb[j];
        if (x > m) { z = z * expf(m - x) + 1.f; m = x; }
        else z += expf(x - m);
    }
    {
        float x = c[b * SS + t];
        if (x > m) { z = z * expf(m - x) + 1.f; m = x; }
        else z += expf(x - m);
    }
    __shared__ float sm[256], sz[256];
    sm[t] = m; sz[t] = z; __syncthreads();
    for (int o = 128; o > 0; o >>= 1) {
        if (t < o) {
            float m1 = sm[t], m2 = sm[t + o];
            float M = fmaxf(m1, m2);
            sz[t] = sz[t] * expf(m1 - M) + sz[t + o] * expf(m2 - M);
            sm[t] = M;
        }
        __syncthreads();
    }
    if (t == 0) { mout[b] = sm[0]; zout[b] = sz[0]; }
}

__global__ __launch_bounds__(256)
void write_outg_kernel(const float* __restrict__ g, const float* __restrict__ m,
                       const float* __restrict__ Z, float* __restrict__ out)
{
    int i = blockIdx.x * 256 + threadIdx.x;
    if (i >= BB * VEXT) return;
    int b = i / VEXT;
    int j = i - b * VEXT;
    out[i] = (j < VV) ? expf(g[(size_t)b * VV + j] - m[b]) / Z[b] : 1e-4f;
}

__global__ __launch_bounds__(256)
void probc_kernel(const float* __restrict__ c, const float* __restrict__ m,
                  const float* __restrict__ Z, float* __restrict__ pc,
                  float* __restrict__ pcsum)
{
    int b = blockIdx.x, t = threadIdx.x;
    float p = expf(c[b * SS + t] - m[b]) / Z[b];
    pc[b * SS + t] = p;
    __shared__ float sm[256];
    sm[t] = p; __syncthreads();
    for (int o = 128; o > 0; o >>= 1) { if (t < o) sm[t] += sm[t + o]; __syncthreads(); }
    if (t == 0) atomicAdd(pcsum, sm[0]);
}

__global__ void zero_pcsum_kernel(float* p) { *p = 0.f; }

__global__ __launch_bounds__(256)
void scatter_kernel(const int* __restrict__ eidx, const float* __restrict__ pc,
                    float* __restrict__ out)
{
    int i = blockIdx.x * 256 + threadIdx.x;
    if (i >= BB * SS) return;
    int b = i >> 8;
    atomicAdd(&out[b * VEXT + eidx[i]], pc[i]);
}

__global__ __launch_bounds__(512)
void weighted_kernel(const int* __restrict__ eidx, const int* __restrict__ iidx,
                     const float* __restrict__ pc, const float* __restrict__ enc,
                     const float* __restrict__ pcsum, float* __restrict__ outw)
{
    int b = blockIdx.x, t = threadIdx.x;
    __shared__ float coef[256];
    __shared__ int cnt;
    if (t == 0) cnt = 0;
    __syncthreads();
    if (t < 256) {
        int match = (eidx[b * SS + t] == iidx[b]);
        coef[t] = match ? pc[b * SS + t] : 0.f;
        if (match) atomicAdd(&cnt, 1);
    }
    __syncthreads();
    float scale = 1.f / (*pcsum);
    if (cnt > 1) scale /= (float)cnt;
    float acc = 0.f;
    const float* eb = enc + (size_t)b * SS * HH + t;
#pragma unroll 4
    for (int s = 0; s < SS; s++) acc += coef[s] * eb[s * HH];
    outw[b * HH + t] = acc * scale;
}

// =========================== launch ===========================
extern "C" void kernel_launch(void* const* d_in, const int* in_sizes, int n_in,
                              void* d_out, int out_size)
{
    const int*   input_idx   = (const int*)  d_in[0];
    const float* encoded     = (const float*)d_in[1];
    const int*   encoded_idx = (const int*)  d_in[2];
    const float* prev_state  = (const float*)d_in[3];
    const float* embed_table = (const float*)d_in[5];
    const float* Ws_w        = (const float*)d_in[6];
    const float* Ws_b        = (const float*)d_in[7];
    const float* gru_Wih     = (const float*)d_in[8];
    const float* gru_Whh     = (const float*)d_in[9];
    const float* gru_bih     = (const float*)d_in[10];
    const float* gru_bhh     = (const float*)d_in[11];
    const float* attn_W      = (const float*)d_in[12];
    const float* attn_b      = (const float*)d_in[13];
    const float* attn_v      = (const float*)d_in[14];
    const float* Wo_w        = (const float*)d_in[15];
    const float* Wo_b        = (const float*)d_in[16];
    const float* Wc_w        = (const float*)d_in[17];
    const float* Wc_b        = (const float*)d_in[18];

    float* out          = (float*)d_out;
    float* out_state    = out + (size_t)BB * VEXT;
    float* out_weighted = out_state + BB * HH;

    float* sc = nullptr;
    cudaGetSymbolAddress((void**)&sc, g_scratch);
    float* xemb   = sc + OFF_XEMB;
    float* prev   = sc + OFF_PREV;
    float* gi     = sc + OFF_GI;
    float* gh     = sc + OFF_GH;
    float* state  = sc + OFF_STATE;
    float* satt   = sc + OFF_SATT;
    float* energy = sc + OFF_ENERGY;
    float* attnw  = sc + OFF_ATTNW;
    float* yv     = sc + OFF_Y;
    float* scoreg = sc + OFF_SCOREG;
    float* scorec = sc + OFF_SCOREC;
    float* probc  = sc + OFF_PROBC;
    float* mrow   = sc + OFF_M;
    float* zrow   = sc + OFF_Z;
    float* pcsum  = sc + OFF_PCSUM;

    __half *enc_h, *y_h, *wo_h, *wc_h, *aw2_h;
    cudaGetSymbolAddress((void**)&enc_h, g_enc_h);
    cudaGetSymbolAddress((void**)&y_h,   g_y_h);
    cudaGetSymbolAddress((void**)&wo_h,  g_wo_h);
    cudaGetSymbolAddress((void**)&wc_h,  g_wc_h);
    cudaGetSymbolAddress((void**)&aw2_h, g_aw2_h);

    cudaFuncSetAttribute(hmma_gemm, cudaFuncAttributeMaxDynamicSharedMemorySize,
                         H_SMEM_DYN);

    // zeros (split-K + atomic accumulators)
    {
        int nz = OFF_SATT + BB * HH - OFF_PREV;
        zero_kernel<<<(nz + 255) / 256, 256>>>(prev, nz);
        zero_kernel<<<(BB * SS + 255) / 256, 256>>>(energy, BB * SS);
        zero_kernel<<<(BB * SS + 255) / 256, 256>>>(scorec, BB * SS);
    }
    // fp16 conversions (independent)
    {
        long t1 = (long)32768 * 512;
        splitA_h<<<(unsigned)((t1 + 255) / 256), 256>>>(encoded, 512, enc_h, 512, t1);
        long t2 = (long)50000 * 1024;
        convB_h<<<(unsigned)((t2 + 255) / 256), 256>>>(Wo_w, 1024, 0, wo_h, 1024, t2);
        long t3 = (long)1024 * 512;
        convB_h<<<(unsigned)((t3 + 255) / 256), 256>>>(Wc_w, 512, 0, wc_h, 512, t3);
        long t4 = (long)512 * 512;
        convB_h<<<(unsigned)((t4 + 255) / 256), 256>>>(attn_W, 1024, 512, aw2_h, 512, t4);
    }
    // GRU chain (FFMA2 small GEMMs)
    gather_embed<<<BB, EE>>>(input_idx, embed_table, xemb);
    gemm128_splitk<<<dim3(HH / 64, 4), 256>>>(prev_state, HH, Ws_w, HH, Ws_b,
                                              prev, HH, HH);
    gemm128_splitk<<<dim3(3 * HH / 64, 4), 256>>>(xemb, EE, gru_Wih, EE + HH,
                                                  gru_bih, gi, 3 * HH, EE);
    gemm128_splitk<<<dim3(3 * HH / 64, 4), 256>>>(prev, HH, gru_Whh, HH,
                                                  gru_bhh, gh, 3 * HH, HH);
    gru_kernel<<<(BB * HH) / 256, 256>>>(gi, gh, prev, state, yv, out_state);
    gemm128_splitk<<<dim3(HH / 64, 4), 256>>>(state, HH, attn_W, 2 * HH,
                                              attn_b, satt, HH, HH);
    // energy: enc_h [32768 x 1024'] @ aw2_h [512 x 512]  (tanh-dot epilogue)
    hmma_gemm<<<dim3(256, 4), 256, H_SMEM_DYN>>>(
        enc_h, 1024, aw2_h, 512, 512, 1,
        satt, 1, 512, attn_v, 0,
        nullptr, 0, energy);
    softmax_s_kernel<<<BB, SS>>>(energy, attnw);
    context_kernel<<<BB, HH>>>(attnw, encoded, yv);
    // split y
    {
        long t5 = (long)128 * 1024;
        splitA_h<<<(unsigned)((t5 + 255) / 256), 256>>>(yv, 1024, y_h, 1024, t5);
    }
    // score_g: y_h [128 x 2048'] @ wo_h [50000 x 1024]  (store epilogue)
    hmma_gemm<<<dim3(1, 391), 256, H_SMEM_DYN>>>(
        y_h, 2048, wo_h, 1024, VV, 0,
        Wo_b, 0, 0, nullptr, 0,
        scoreg, VV, nullptr);
    // score_c: enc_h @ wc_h [1024 x 512]  (tanh-dot epilogue)
    hmma_gemm<<<dim3(256, 8), 256, H_SMEM_DYN>>>(
        enc_h, 1024, wc_h, 512, 1024, 1,
        Wc_b, 0, 1024, yv, 1,
        nullptr, 0, scorec);
    mask_kernel<<<(BB * SS + 255) / 256, 256>>>(encoded_idx, scorec);
    // softmax over concat + outputs
    rowmaxsum_kernel<<<BB, 256>>>(scoreg, scorec, mrow, zrow);
    write_outg_kernel<<<(BB * VEXT + 255) / 256, 256>>>(scoreg, mrow, zrow, out);
    zero_pcsum_kernel<<<1, 1>>>(pcsum);
    probc_kernel<<<BB, SS>>>(scorec, mrow, zrow, probc, pcsum);
    scatter_kernel<<<(BB * SS) / 256, 256>>>(encoded_idx, probc, out);
    weighted_kernel<<<BB, HH>>>(encoded_idx, input_idx, probc, encoded,
                                pcsum, out_weighted);
}